// round 1
// baseline (speedup 1.0000x reference)
#include <cuda_runtime.h>
#include <cuda_bf16.h>

#define NENT   100000
#define NEDGE  500000
#define NSEED  10000
#define DIM    128
#define NBLK_SCAN 98   // ceil(100000/1024)

// ---------------- scratch (static device globals: allowed) ----------------
__device__ int   g_cnt[NENT];
__device__ int   g_rowptr[NENT + 1];
__device__ int   g_cursor[NENT];
__device__ int   g_col[2 * NEDGE];
__device__ float g_rinv[NENT];
__device__ float g_agg[(size_t)NENT * DIM];
__device__ float g_hid[(size_t)NENT * DIM];
__device__ int   g_bsum[128];

// ---------------- graph build ----------------
__global__ void k_init() {
    int i = blockIdx.x * blockDim.x + threadIdx.x;
    if (i < NENT) g_cnt[i] = 0;
}

__global__ void k_count(const int* __restrict__ edges) {
    int i = blockIdx.x * blockDim.x + threadIdx.x;
    if (i < NEDGE) {
        int a = edges[2 * i], b = edges[2 * i + 1];
        atomicAdd(&g_cnt[a], 1);
        atomicAdd(&g_cnt[b], 1);
    }
}

// block-level inclusive scan (Hillis-Steele), emit exclusive + block sums
__global__ void k_scan1() {
    __shared__ int s[1024];
    int i = blockIdx.x * 1024 + threadIdx.x;
    int v = (i < NENT) ? g_cnt[i] : 0;
    s[threadIdx.x] = v;
    __syncthreads();
    #pragma unroll
    for (int off = 1; off < 1024; off <<= 1) {
        int t = (threadIdx.x >= off) ? s[threadIdx.x - off] : 0;
        __syncthreads();
        s[threadIdx.x] += t;
        __syncthreads();
    }
    if (i < NENT) g_rowptr[i] = s[threadIdx.x] - v;
    if (threadIdx.x == 1023) g_bsum[blockIdx.x] = s[1023];
}

__global__ void k_scan2() {
    int run = 0;
    for (int b = 0; b < NBLK_SCAN; b++) {
        int t = g_bsum[b];
        g_bsum[b] = run;
        run += t;
    }
}

__global__ void k_scan3() {
    int i = blockIdx.x * blockDim.x + threadIdx.x;
    if (i < NENT) g_rowptr[i] += g_bsum[i >> 10];
    if (i == 0) g_rowptr[NENT] = 2 * NEDGE;
}

__global__ void k_prep() {
    int i = blockIdx.x * blockDim.x + threadIdx.x;
    if (i < NENT) {
        g_rinv[i]   = rsqrtf((float)(g_cnt[i] + 1));  // +1 = self loop
        g_cursor[i] = g_rowptr[i];
    }
}

__global__ void k_fill(const int* __restrict__ edges) {
    int i = blockIdx.x * blockDim.x + threadIdx.x;
    if (i < NEDGE) {
        int a = edges[2 * i], b = edges[2 * i + 1];
        int p = atomicAdd(&g_cursor[b], 1); g_col[p] = a;
        int q = atomicAdd(&g_cursor[a], 1); g_col[q] = b;
    }
}

// ---------------- aggregation: agg[v] = sum_u x[u]*rinv[u]*rinv[v] + x[v]*rinv[v]^2 ----------------
__global__ void k_agg(const float* __restrict__ x) {
    int gw   = (blockIdx.x * blockDim.x + threadIdx.x) >> 5;
    int lane = threadIdx.x & 31;
    if (gw >= NENT) return;
    int v = gw;
    int beg = g_rowptr[v], end = g_rowptr[v + 1];
    float rv = g_rinv[v];
    const float4* x4 = (const float4*)x;
    float4 a = x4[(size_t)v * 32 + lane];
    float selfn = rv * rv;
    float4 acc;
    acc.x = a.x * selfn; acc.y = a.y * selfn; acc.z = a.z * selfn; acc.w = a.w * selfn;
    for (int e = beg; e < end; e++) {
        int u = g_col[e];
        float nm = rv * g_rinv[u];
        float4 xu = x4[(size_t)u * 32 + lane];
        acc.x = fmaf(xu.x, nm, acc.x);
        acc.y = fmaf(xu.y, nm, acc.y);
        acc.z = fmaf(xu.z, nm, acc.z);
        acc.w = fmaf(xu.w, nm, acc.w);
    }
    ((float4*)g_agg)[(size_t)v * 32 + lane] = acc;
}

// ---------------- dense: out = relu(g_agg @ W + xin) ----------------
// warp handles 4 rows; lane owns cols {lane, lane+32, lane+64, lane+96}
__global__ void k_dense(const float* __restrict__ xin, const float* __restrict__ W,
                        float* __restrict__ out) {
    extern __shared__ float Ws[];  // 128*128 floats = 64 KB
    for (int i = threadIdx.x; i < DIM * DIM; i += blockDim.x) Ws[i] = W[i];
    __syncthreads();

    int lane = threadIdx.x & 31;
    int gw   = blockIdx.x * (blockDim.x >> 5) + (threadIdx.x >> 5);
    int nw   = gridDim.x * (blockDim.x >> 5);

    for (int base = gw * 4; base < NENT; base += nw * 4) {
        float a[4][4];
        #pragma unroll
        for (int j = 0; j < 4; j++)
            #pragma unroll
            for (int q = 0; q < 4; q++)
                a[j][q] = g_agg[(size_t)(base + j) * DIM + q * 32 + lane];

        float acc[4][4];
        #pragma unroll
        for (int j = 0; j < 4; j++)
            #pragma unroll
            for (int c = 0; c < 4; c++) acc[j][c] = 0.f;

        #pragma unroll
        for (int q = 0; q < 4; q++) {
            #pragma unroll 8
            for (int kk = 0; kk < 32; kk++) {
                int k = q * 32 + kk;
                float w0 = Ws[k * DIM + lane];
                float w1 = Ws[k * DIM + 32 + lane];
                float w2 = Ws[k * DIM + 64 + lane];
                float w3 = Ws[k * DIM + 96 + lane];
                #pragma unroll
                for (int j = 0; j < 4; j++) {
                    float av = __shfl_sync(0xffffffffu, a[j][q], kk);
                    acc[j][0] = fmaf(av, w0, acc[j][0]);
                    acc[j][1] = fmaf(av, w1, acc[j][1]);
                    acc[j][2] = fmaf(av, w2, acc[j][2]);
                    acc[j][3] = fmaf(av, w3, acc[j][3]);
                }
            }
        }

        #pragma unroll
        for (int j = 0; j < 4; j++)
            #pragma unroll
            for (int c = 0; c < 4; c++) {
                size_t idx = (size_t)(base + j) * DIM + c * 32 + lane;
                out[idx] = fmaxf(acc[j][c] + xin[idx], 0.f);
            }
    }
}

// ---------------- seed gather ----------------
__global__ void k_seed(const int* __restrict__ seeds, const float* __restrict__ ent,
                       float* __restrict__ out) {
    int gw   = (blockIdx.x * blockDim.x + threadIdx.x) >> 5;
    int lane = threadIdx.x & 31;
    if (gw >= NSEED) return;
    int s = seeds[gw];
    ((float4*)out)[(size_t)gw * 32 + lane] = ((const float4*)ent)[(size_t)s * 32 + lane];
}

// ---------------- launch ----------------
static void run_graph(const int* edges, const float* emb, const int* seeds,
                      float* hid, float* ent_out, float* seed_out,
                      const float* W1, const float* W2) {
    int tE = (NEDGE + 255) / 256;
    int tN = (NENT + 255) / 256;
    k_init <<<tN, 256>>>();
    k_count<<<tE, 256>>>(edges);
    k_scan1<<<NBLK_SCAN, 1024>>>();
    k_scan2<<<1, 1>>>();
    k_scan3<<<tN, 256>>>();
    k_prep <<<tN, 256>>>();
    k_fill <<<tE, 256>>>(edges);

    // layer 1: agg(emb) -> hid = relu(agg@W1 + emb)
    k_agg  <<<(NENT * 32) / 256, 256>>>(emb);
    k_dense<<<444, 256, 65536>>>(emb, W1, hid);
    // layer 2: agg(hid) -> ent_out = relu(agg@W2 + hid)
    k_agg  <<<(NENT * 32) / 256, 256>>>(hid);
    k_dense<<<444, 256, 65536>>>(hid, W2, ent_out);

    k_seed <<<(NSEED * 32 + 255) / 256, 256>>>(seeds, ent_out, seed_out);
}

extern "C" void kernel_launch(void* const* d_in, const int* in_sizes, int n_in,
                              void* d_out, int out_size) {
    const int*   sr_seeds = (const int*)d_in[0];
    const int*   tg_seeds = (const int*)d_in[1];
    const float* emb_sr   = (const float*)d_in[4];
    const float* emb_tg   = (const float*)d_in[5];
    const int*   edges_sr = (const int*)d_in[6];
    const int*   edges_tg = (const int*)d_in[7];
    const float* W1       = (const float*)d_in[8];
    const float* W2       = (const float*)d_in[9];

    float* out         = (float*)d_out;
    float* sr_seed_out = out;
    float* tg_seed_out = out + (size_t)NSEED * DIM;
    float* sr_ent_out  = out + (size_t)2 * NSEED * DIM;
    float* tg_ent_out  = out + (size_t)2 * NSEED * DIM + (size_t)NENT * DIM;

    cudaFuncSetAttribute(k_dense, cudaFuncAttributeMaxDynamicSharedMemorySize, 65536);

    float* hid = nullptr;
    cudaGetSymbolAddress((void**)&hid, g_hid);

    run_graph(edges_sr, emb_sr, sr_seeds, hid, sr_ent_out, sr_seed_out, W1, W2);
    run_graph(edges_tg, emb_tg, tg_seeds, hid, tg_ent_out, tg_seed_out, W1, W2);
}